// round 2
// baseline (speedup 1.0000x reference)
#include <cuda_runtime.h>

// Problem constants
#define NK 3
#define NB 8
#define NT 1024
#define ND 1024
#define NR 32
#define ROWS_K (NB * NT)          // 8192 rows per area
#define ROWS_ALL (NK * ROWS_K)    // 24576 rows total
#define YN ((size_t)ROWS_ALL * ND) // 25165824 output elems for y

// ---------------- scratch (device globals; no allocation allowed) -------------
__device__ float g_amp[24 * 8 * 1024];                  // partial sums for area means
__device__ float g_pm[NB * NK * ND];                    // [b][k*d+n] gelu(am @ projW + b)
__device__ float g_h0[NB * NK * ND];                    // LN output [B, 3072]
__device__ float g_h1[NB * 2 * ND];                     // [B, 2048]
__device__ float g_alpha[NB * NK];                      // softmax weights
__device__ float g_low[(size_t)ROWS_ALL * NR];          // [K*B*T, 32]
__device__ float g_routed[(size_t)ROWS_K * ND];         // [B*T, d]
__device__ float g_bcomp[(size_t)ROWS_ALL * ND];
__device__ float g_ah[(size_t)ROWS_ALL * ND];
__device__ float g_gate[(size_t)ROWS_ALL * ND];
__device__ float g_m[(size_t)ROWS_ALL * ND];

// ---------------- helpers -----------------------------------------------------
__device__ __forceinline__ float gelu_f(float x) {
    return 0.5f * x * (1.0f + erff(x * 0.7071067811865476f));
}
__device__ __forceinline__ float sigm_f(float x) {
    return 1.0f / (1.0f + expf(-x));
}

__device__ __forceinline__ float2 blockReduce2(float a, float b) {
    __shared__ float sa[8], sb[8];
    int lane = threadIdx.x & 31;
    int w = threadIdx.x >> 5;
#pragma unroll
    for (int o = 16; o > 0; o >>= 1) {
        a += __shfl_xor_sync(0xffffffffu, a, o);
        b += __shfl_xor_sync(0xffffffffu, b, o);
    }
    if (lane == 0) { sa[w] = a; sb[w] = b; }
    __syncthreads();
    if (w == 0) {
        a = (lane < 8) ? sa[lane] : 0.f;
        b = (lane < 8) ? sb[lane] : 0.f;
#pragma unroll
        for (int o = 4; o > 0; o >>= 1) {
            a += __shfl_xor_sync(0xffffffffu, a, o);
            b += __shfl_xor_sync(0xffffffffu, b, o);
        }
        if (lane == 0) { sa[0] = a; sb[0] = b; }
    }
    __syncthreads();
    return make_float2(sa[0], sb[0]);
}

// ---------------- stage 1: area means (partial sums over T chunks) ------------
__global__ void __launch_bounds__(256) kMeans(const float* __restrict__ X) {
    int slab = blockIdx.x;       // k*8+b, 0..23
    int chunk = blockIdx.y;      // 0..7 (128 t each)
    size_t base = (size_t)slab * (NT * ND) + (size_t)chunk * 128 * ND;
    int col = threadIdx.x * 4;
    float4 acc = make_float4(0.f, 0.f, 0.f, 0.f);
#pragma unroll 4
    for (int t = 0; t < 128; t++) {
        float4 v = *(const float4*)(X + base + (size_t)t * ND + col);
        acc.x += v.x; acc.y += v.y; acc.z += v.z; acc.w += v.w;
    }
    *(float4*)&g_amp[(size_t)slab * 8192 + (size_t)chunk * 1024 + col] = acc;
}

// ---------------- stage 2: pm = gelu(am @ projW + projB) ----------------------
__global__ void __launch_bounds__(256) kPm(const float* __restrict__ W,
                                           const float* __restrict__ bvec) {
    __shared__ float s[1024];
    int bid = blockIdx.x;        // b*3 + k
    int b = bid / 3, k = bid % 3;
    int slab = k * 8 + b;
    for (int i = threadIdx.x; i < 1024; i += 256) {
        float acc = 0.f;
#pragma unroll
        for (int c = 0; c < 8; c++) acc += g_amp[(size_t)slab * 8192 + c * 1024 + i];
        s[i] = acc * (1.0f / 1024.0f);
    }
    __syncthreads();
    int n = threadIdx.x * 4;
    float4 acc = *(const float4*)(bvec + n);
#pragma unroll 4
    for (int dd = 0; dd < 1024; dd++) {
        float a = s[dd];
        float4 w = *(const float4*)(W + (size_t)dd * 1024 + n);
        acc.x += a * w.x; acc.y += a * w.y; acc.z += a * w.z; acc.w += a * w.w;
    }
    acc.x = gelu_f(acc.x); acc.y = gelu_f(acc.y); acc.z = gelu_f(acc.z); acc.w = gelu_f(acc.w);
    *(float4*)&g_pm[(size_t)bid * 1024 + n] = acc;
}

// ---------------- stage 3: LN over K*d=3072 per batch -------------------------
__global__ void __launch_bounds__(256) kLN1(const float* __restrict__ gvec,
                                            const float* __restrict__ bvec) {
    int b = blockIdx.x;
    size_t base = (size_t)b * 3072;
    int i0 = threadIdx.x * 4;
    float4 v[3];
    float s = 0.f, sq = 0.f;
#pragma unroll
    for (int c = 0; c < 3; c++) {
        v[c] = *(const float4*)&g_pm[base + c * 1024 + i0];
        s += v[c].x + v[c].y + v[c].z + v[c].w;
        sq += v[c].x * v[c].x + v[c].y * v[c].y + v[c].z * v[c].z + v[c].w * v[c].w;
    }
    float2 r = blockReduce2(s, sq);
    float mu = r.x * (1.0f / 3072.0f);
    float var = r.y * (1.0f / 3072.0f) - mu * mu;
    float rstd = rsqrtf(var + 1e-5f);
#pragma unroll
    for (int c = 0; c < 3; c++) {
        int idx = c * 1024 + i0;
        float4 G = *(const float4*)(gvec + idx);
        float4 Bv = *(const float4*)(bvec + idx);
        float4 o;
        o.x = (v[c].x - mu) * rstd * G.x + Bv.x;
        o.y = (v[c].y - mu) * rstd * G.y + Bv.y;
        o.z = (v[c].z - mu) * rstd * G.z + Bv.z;
        o.w = (v[c].w - mu) * rstd * G.w + Bv.w;
        *(float4*)&g_h0[base + idx] = o;
    }
}

// ---------------- stage 4: h1 = gelu(h0 @ W1 + b1) ----------------------------
__global__ void __launch_bounds__(256) kH1(const float* __restrict__ W1,
                                           const float* __restrict__ b1) {
    __shared__ float s[3072];
    int b = blockIdx.y;
    int n = blockIdx.x * 256 + threadIdx.x;
    for (int i = threadIdx.x; i < 3072; i += 256) s[i] = g_h0[(size_t)b * 3072 + i];
    __syncthreads();
    float acc = b1[n];
#pragma unroll 4
    for (int dd = 0; dd < 3072; dd++) acc += s[dd] * W1[(size_t)dd * 2048 + n];
    g_h1[(size_t)b * 2048 + n] = gelu_f(acc);
}

// ---------------- stage 5: logits + softmax alpha -----------------------------
__global__ void __launch_bounds__(256) kLogits(const float* __restrict__ W2,
                                               const float* __restrict__ b2,
                                               const float* __restrict__ gum,
                                               float* __restrict__ outLog) {
    __shared__ float s0[256], s1[256], s2[256];
    int b = blockIdx.x;
    int tid = threadIdx.x;
    float a0 = 0.f, a1 = 0.f, a2 = 0.f;
    for (int dd = tid; dd < 2048; dd += 256) {
        float v = g_h1[(size_t)b * 2048 + dd];
        a0 += v * W2[dd * 3 + 0];
        a1 += v * W2[dd * 3 + 1];
        a2 += v * W2[dd * 3 + 2];
    }
    s0[tid] = a0; s1[tid] = a1; s2[tid] = a2;
    __syncthreads();
    for (int off = 128; off > 0; off >>= 1) {
        if (tid < off) { s0[tid] += s0[tid + off]; s1[tid] += s1[tid + off]; s2[tid] += s2[tid + off]; }
        __syncthreads();
    }
    if (tid == 0) {
        float lg[3];
        lg[0] = s0[0] + b2[0]; lg[1] = s1[0] + b2[1]; lg[2] = s2[0] + b2[2];
        float z[3];
#pragma unroll
        for (int j = 0; j < 3; j++) {
            outLog[b * 3 + j] = lg[j];
            z[j] = (lg[j] + gum[b * 3 + j]) * 1.25f;   // / TAU (0.8)
        }
        float m = fmaxf(z[0], fmaxf(z[1], z[2]));
        float e0 = expf(z[0] - m), e1 = expf(z[1] - m), e2 = expf(z[2] - m);
        float inv = 1.0f / (e0 + e1 + e2);
        g_alpha[b * 3 + 0] = e0 * inv;
        g_alpha[b * 3 + 1] = e1 * inv;
        g_alpha[b * 3 + 2] = e2 * inv;
    }
}

// ---------------- stage 6: low = X @ V  ([64 rows x 32] tiles) ----------------
__global__ void __launch_bounds__(256) kLow(const float* __restrict__ X,
                                            const float* __restrict__ V) {
    __shared__ float Xs[64][33];
    __shared__ float Vs[32][32];
    int row0 = blockIdx.x * 64;            // global row in [0, 24576)
    int k = row0 >> 13;                    // / 8192
    int tid = threadIdx.x;
    int tx = tid & 31, ty = tid >> 5;      // tx: r, ty: row group (8)
    float acc[8];
#pragma unroll
    for (int i = 0; i < 8; i++) acc[i] = 0.f;

    for (int d0 = 0; d0 < 1024; d0 += 32) {
#pragma unroll
        for (int i = 0; i < 8; i++) {
            int idx = tid + i * 256;
            int r = idx >> 5, c = idx & 31;
            Xs[r][c] = X[(size_t)(row0 + r) * ND + d0 + c];
        }
#pragma unroll
        for (int i = 0; i < 4; i++) {
            int idx = tid + i * 256;
            int dd = idx >> 5, rr = idx & 31;
            Vs[dd][rr] = V[((size_t)k * 1024 + d0 + dd) * 32 + rr];
        }
        __syncthreads();
#pragma unroll
        for (int dd = 0; dd < 32; dd++) {
            float vv = Vs[dd][tx];
#pragma unroll
            for (int rr = 0; rr < 8; rr++) acc[rr] += Xs[rr * 8 + ty][dd] * vv;
        }
        __syncthreads();
    }
#pragma unroll
    for (int rr = 0; rr < 8; rr++)
        g_low[(size_t)(row0 + rr * 8 + ty) * 32 + tx] = acc[rr];
}

// ---------------- stage 7: routed = sum_k alpha * low @ U^T -------------------
__global__ void __launch_bounds__(256) kRouted(const float* __restrict__ U) {
    __shared__ float As[96][64];   // [p][row]
    __shared__ float Us[96][64];   // [p][col]
    int col0 = blockIdx.x * 64;
    int row0 = blockIdx.y * 64;    // row in [0, 8192)
    int tid = threadIdx.x;
    int tx = tid & 15, ty = tid >> 4;

    for (int idx = tid; idx < 6144; idx += 256) {
        int r0 = idx / 96, p = idx - r0 * 96;
        int k = p >> 5, rr = p & 31;
        int row = row0 + r0;
        int b = row >> 10;
        As[p][r0] = g_alpha[b * 3 + k] * g_low[((size_t)k * 8192 + row) * 32 + rr];
    }
    for (int idx = tid; idx < 6144; idx += 256) {
        int p = idx >> 6, e = idx & 63;
        int k = p >> 5, rr = p & 31;
        Us[p][e] = U[((size_t)k * 1024 + col0 + e) * 32 + rr];
    }
    __syncthreads();

    float acc[4][4];
#pragma unroll
    for (int i = 0; i < 4; i++)
#pragma unroll
        for (int j = 0; j < 4; j++) acc[i][j] = 0.f;

#pragma unroll 8
    for (int p = 0; p < 96; p++) {
        float4 u4 = *(const float4*)&Us[p][tx * 4];
        float a0 = As[p][ty * 4 + 0], a1 = As[p][ty * 4 + 1];
        float a2 = As[p][ty * 4 + 2], a3 = As[p][ty * 4 + 3];
        acc[0][0] += a0 * u4.x; acc[0][1] += a0 * u4.y; acc[0][2] += a0 * u4.z; acc[0][3] += a0 * u4.w;
        acc[1][0] += a1 * u4.x; acc[1][1] += a1 * u4.y; acc[1][2] += a1 * u4.z; acc[1][3] += a1 * u4.w;
        acc[2][0] += a2 * u4.x; acc[2][1] += a2 * u4.y; acc[2][2] += a2 * u4.z; acc[2][3] += a2 * u4.w;
        acc[3][0] += a3 * u4.x; acc[3][1] += a3 * u4.y; acc[3][2] += a3 * u4.z; acc[3][3] += a3 * u4.w;
    }
#pragma unroll
    for (int i = 0; i < 4; i++) {
        float4 o = make_float4(acc[i][0], acc[i][1], acc[i][2], acc[i][3]);
        *(float4*)&g_routed[(size_t)(row0 + ty * 4 + i) * ND + col0 + tx * 4] = o;
    }
}

// ---------------- generic 128x128x8 fp32 GEMM with fused epilogues ------------
// asel: 0=X(input), 1=routed, 2=bcomp, 3=ah
// csel: 0=bcomp, 1=ah, 2=gate, 3=m
// mode: 0=store, 1=gelu, 2=sigmoid(prevC + v + bias), 3=prevC * gelu(v)
__global__ void __launch_bounds__(256, 2) gemm_k(
    const float* __restrict__ Xp,
    const float* __restrict__ W, size_t wOff, size_t wStride,
    const float* __restrict__ bias,
    int asel, int csel, int mode)
{
    const int z = blockIdx.z;
    const float* Ab;
    size_t aStride;
    if (asel == 0)      { Ab = Xp;       aStride = (size_t)ROWS_K * ND; }
    else if (asel == 1) { Ab = g_routed; aStride = 0; }
    else if (asel == 2) { Ab = g_bcomp;  aStride = (size_t)ROWS_K * ND; }
    else                { Ab = g_ah;     aStride = (size_t)ROWS_K * ND; }
    float* Cb;
    if (csel == 0)      Cb = g_bcomp;
    else if (csel == 1) Cb = g_ah;
    else if (csel == 2) Cb = g_gate;
    else                Cb = g_m;

    const int N = ND, Kd = ND;
    Ab += (size_t)z * aStride + (size_t)(blockIdx.y * 128) * Kd;
    const float* Wp = W + wOff + (size_t)z * wStride + blockIdx.x * 128;
    Cb += (size_t)z * ROWS_K * ND + (size_t)(blockIdx.y * 128) * N + blockIdx.x * 128;

    __shared__ float As[2][8][128];
    __shared__ float Bs[2][8][128];

    const int tid = threadIdx.x;
    const int tx = tid & 15, ty = tid >> 4;
    const int arow = tid >> 1, acol = (tid & 1) * 4;
    const int brow = tid >> 5, bcol = (tid & 31) * 4;

    float4 aR = *(const float4*)(Ab + (size_t)arow * Kd + acol);
    float4 bR = *(const float4*)(Wp + (size_t)brow * N + bcol);
    As[0][acol + 0][arow] = aR.x; As[0][acol + 1][arow] = aR.y;
    As[0][acol + 2][arow] = aR.z; As[0][acol + 3][arow] = aR.w;
    *(float4*)&Bs[0][brow][bcol] = bR;
    __syncthreads();

    float acc[8][8];
#pragma unroll
    for (int i = 0; i < 8; i++)
#pragma unroll
        for (int j = 0; j < 8; j++) acc[i][j] = 0.f;

    const int kTiles = Kd >> 3;
    for (int kt = 0; kt < kTiles; kt++) {
        const int cur = kt & 1;
        if (kt + 1 < kTiles) {
            aR = *(const float4*)(Ab + (size_t)arow * Kd + (kt + 1) * 8 + acol);
            bR = *(const float4*)(Wp + ((size_t)(kt + 1) * 8 + brow) * N + bcol);
        }
#pragma unroll
        for (int kk = 0; kk < 8; kk++) {
            float a[8], b[8];
            *(float4*)&a[0] = *(const float4*)&As[cur][kk][ty * 4];
            *(float4*)&a[4] = *(const float4*)&As[cur][kk][64 + ty * 4];
            *(float4*)&b[0] = *(const float4*)&Bs[cur][kk][tx * 4];
            *(float4*)&b[4] = *(const float4*)&Bs[cur][kk][64 + tx * 4];
#pragma unroll
            for (int i = 0; i < 8; i++)
#pragma unroll
                for (int j = 0; j < 8; j++) acc[i][j] += a[i] * b[j];
        }
        if (kt + 1 < kTiles) {
            const int nb = cur ^ 1;
            As[nb][acol + 0][arow] = aR.x; As[nb][acol + 1][arow] = aR.y;
            As[nb][acol + 2][arow] = aR.z; As[nb][acol + 3][arow] = aR.w;
            *(float4*)&Bs[nb][brow][bcol] = bR;
        }
        __syncthreads();
    }

    // epilogue
#pragma unroll
    for (int ih = 0; ih < 2; ih++)
#pragma unroll
        for (int ir = 0; ir < 4; ir++) {
            int row = ih * 64 + ty * 4 + ir;
#pragma unroll
            for (int jh = 0; jh < 2; jh++) {
                int col = jh * 64 + tx * 4;
                float4 v;
                v.x = acc[ih * 4 + ir][jh * 4 + 0];
                v.y = acc[ih * 4 + ir][jh * 4 + 1];
                v.z = acc[ih * 4 + ir][jh * 4 + 2];
                v.w = acc[ih * 4 + ir][jh * 4 + 3];
                float* cp = Cb + (size_t)row * N + col;
                if (mode == 1) {
                    v.x = gelu_f(v.x); v.y = gelu_f(v.y); v.z = gelu_f(v.z); v.w = gelu_f(v.w);
                } else if (mode == 2) {
                    float4 p = *(float4*)cp;
                    float4 bi = *(const float4*)(bias + (size_t)z * ND + blockIdx.x * 128 + col);
                    v.x = sigm_f(p.x + v.x + bi.x);
                    v.y = sigm_f(p.y + v.y + bi.y);
                    v.z = sigm_f(p.z + v.z + bi.z);
                    v.w = sigm_f(p.w + v.w + bi.w);
                } else if (mode == 3) {
                    float4 p = *(float4*)cp;
                    v.x = p.x * gelu_f(v.x); v.y = p.y * gelu_f(v.y);
                    v.z = p.z * gelu_f(v.z); v.w = p.w * gelu_f(v.w);
                }
                *(float4*)cp = v;
            }
        }
}

// ---------------- final: y = LN(x + (1-g)*b + g*m) * lng + lnb ----------------
__global__ void __launch_bounds__(256) kFinal(const float* __restrict__ X,
                                              const float* __restrict__ cg,
                                              const float* __restrict__ cb,
                                              float* __restrict__ out) {
    size_t row = blockIdx.x;
    int k = (int)(row >> 13);
    size_t base = row * ND + threadIdx.x * 4;
    float4 x  = *(const float4*)(X + base);
    float4 bc = *(const float4*)(g_bcomp + base);
    float4 gv = *(const float4*)(g_gate + base);
    float4 mv = *(const float4*)(g_m + base);
    float4 v;
    v.x = x.x + (1.f - gv.x) * bc.x + gv.x * mv.x;
    v.y = x.y + (1.f - gv.y) * bc.y + gv.y * mv.y;
    v.z = x.z + (1.f - gv.z) * bc.z + gv.z * mv.z;
    v.w = x.w + (1.f - gv.w) * bc.w + gv.w * mv.w;
    float s = v.x + v.y + v.z + v.w;
    float sq = v.x * v.x + v.y * v.y + v.z * v.z + v.w * v.w;
    float2 r = blockReduce2(s, sq);
    float mu = r.x * (1.0f / 1024.0f);
    float var = r.y * (1.0f / 1024.0f) - mu * mu;
    float rstd = rsqrtf(var + 1e-5f);
    int ci = k * 1024 + threadIdx.x * 4;
    float4 G = *(const float4*)(cg + ci);
    float4 Bv = *(const float4*)(cb + ci);
    float4 o;
    o.x = (v.x - mu) * rstd * G.x + Bv.x;
    o.y = (v.y - mu) * rstd * G.y + Bv.y;
    o.z = (v.z - mu) * rstd * G.z + Bv.z;
    o.w = (v.w - mu) * rstd * G.w + Bv.w;
    *(float4*)(out + base) = o;
}

// ---------------- launch ------------------------------------------------------
extern "C" void kernel_launch(void* const* d_in, const int* in_sizes, int n_in,
                              void* d_out, int out_size) {
    (void)in_sizes; (void)n_in; (void)out_size;
    const float* X    = (const float*)d_in[0];
    const float* gum  = (const float*)d_in[1];
    const float* prW  = (const float*)d_in[2];
    const float* prB  = (const float*)d_in[3];
    const float* hlg  = (const float*)d_in[4];
    const float* hlb  = (const float*)d_in[5];
    const float* W1   = (const float*)d_in[6];
    const float* b1   = (const float*)d_in[7];
    const float* W2   = (const float*)d_in[8];
    const float* b2   = (const float*)d_in[9];
    const float* U    = (const float*)d_in[10];
    const float* V    = (const float*)d_in[11];
    const float* Wb   = (const float*)d_in[12];
    const float* Wa   = (const float*)d_in[13];
    const float* Wg   = (const float*)d_in[14];
    const float* bg   = (const float*)d_in[15];
    const float* Wm1  = (const float*)d_in[16];
    const float* Wm2  = (const float*)d_in[17];
    const float* clg  = (const float*)d_in[18];
    const float* clb  = (const float*)d_in[19];
    float* out = (float*)d_out;

    // controller
    kMeans<<<dim3(24, 8), 256>>>(X);
    kPm<<<24, 256>>>(prW, prB);
    kLN1<<<8, 256>>>(hlg, hlb);
    kH1<<<dim3(8, 8), 256>>>(W1, b1);
    kLogits<<<8, 256>>>(W2, b2, gum, out + YN);

    // router
    kLow<<<ROWS_ALL / 64, 256>>>(X, V);
    kRouted<<<dim3(16, 128), 256>>>(U);

    // columns: pass 1
    dim3 gg(8, 64, 3);
    gemm_k<<<gg, 256>>>(X, Wb,  0,       1048576, nullptr, 0, 0, 1); // bcomp = gelu(X@Wb)
    gemm_k<<<gg, 256>>>(X, Wa,  0,       1048576, nullptr, 1, 1, 1); // ah = gelu(routed@Wa)
    gemm_k<<<gg, 256>>>(X, Wg,  0,       2097152, nullptr, 0, 2, 0); // gate += X@Wg_top
    gemm_k<<<gg, 256>>>(X, Wg,  1048576, 2097152, bg,      1, 2, 2); // gate = sigmoid(. + routed@Wg_bot + bg)
    // pass 2
    gemm_k<<<gg, 256>>>(X, Wm1, 0,       1048576, nullptr, 2, 3, 1); // m = gelu(bcomp@Wm1)
    gemm_k<<<gg, 256>>>(X, Wm2, 0,       1048576, nullptr, 3, 3, 3); // m *= gelu(ah@Wm2)

    // final LN + output
    kFinal<<<ROWS_ALL, 256>>>(X, clg, clb, out);
}

// round 5
// speedup vs baseline: 1.5832x; 1.5832x over previous
#include <cuda_runtime.h>
#include <cuda_bf16.h>

// Problem constants
#define NK 3
#define NB 8
#define NT 1024
#define ND 1024
#define NR 32
#define ROWS_K (NB * NT)          // 8192 rows per area
#define ROWS_ALL (NK * ROWS_K)    // 24576 rows total
#define YN ((size_t)ROWS_ALL * ND) // output elems for y

// ---------------- scratch (device globals; no allocation allowed) -------------
__device__ float g_amp[24 * 8 * 1024];                  // partial sums for area means
__device__ float g_am[24 * 1024];                       // area means, bid-ordered
__device__ float g_pm[NB * NK * ND];                    // gelu(am @ projW + b)
__device__ float g_h0[NB * NK * ND];                    // LN output [B, 3072]
__device__ float g_h1[NB * 2 * ND];                     // [B, 2048]
__device__ float g_alpha[NB * NK];                      // softmax weights
__device__ float g_low[(size_t)ROWS_ALL * NR];          // [K*B*T, 32]
__device__ float g_routed[(size_t)ROWS_K * ND];         // [B*T, d]
__device__ float g_bcomp[(size_t)ROWS_ALL * ND];
__device__ float g_ah[(size_t)ROWS_ALL * ND];
__device__ float g_gate[(size_t)ROWS_ALL * ND];
__device__ float g_m[(size_t)ROWS_ALL * ND];

// ---------------- helpers -----------------------------------------------------
__device__ __forceinline__ float gelu_f(float x) {
    return 0.5f * x * (1.0f + erff(x * 0.7071067811865476f));
}
__device__ __forceinline__ float sigm_f(float x) {
    return 1.0f / (1.0f + expf(-x));
}

// split two floats into packed-bf16 hi and lo words (element0 in low 16 bits)
__device__ __forceinline__ void split2(float x, float y, unsigned &hi, unsigned &lo) {
    __nv_bfloat16 hx = __float2bfloat16_rn(x);
    __nv_bfloat16 hy = __float2bfloat16_rn(y);
    float rx = x - __bfloat162float(hx);
    float ry = y - __bfloat162float(hy);
    __nv_bfloat16 lx = __float2bfloat16_rn(rx);
    __nv_bfloat16 ly = __float2bfloat16_rn(ry);
    hi = (unsigned)__bfloat16_as_ushort(hx) | ((unsigned)__bfloat16_as_ushort(hy) << 16);
    lo = (unsigned)__bfloat16_as_ushort(lx) | ((unsigned)__bfloat16_as_ushort(ly) << 16);
}

__device__ __forceinline__ void mma16816(float* c, const unsigned* a, unsigned b0, unsigned b1) {
    asm volatile(
        "mma.sync.aligned.m16n8k16.row.col.f32.bf16.bf16.f32 "
        "{%0,%1,%2,%3}, {%4,%5,%6,%7}, {%8,%9}, {%0,%1,%2,%3};"
        : "+f"(c[0]), "+f"(c[1]), "+f"(c[2]), "+f"(c[3])
        : "r"(a[0]), "r"(a[1]), "r"(a[2]), "r"(a[3]), "r"(b0), "r"(b1));
}

__device__ __forceinline__ float2 blockReduce2(float a, float b) {
    __shared__ float sa[8], sb[8];
    int lane = threadIdx.x & 31;
    int w = threadIdx.x >> 5;
#pragma unroll
    for (int o = 16; o > 0; o >>= 1) {
        a += __shfl_xor_sync(0xffffffffu, a, o);
        b += __shfl_xor_sync(0xffffffffu, b, o);
    }
    if (lane == 0) { sa[w] = a; sb[w] = b; }
    __syncthreads();
    if (w == 0) {
        a = (lane < 8) ? sa[lane] : 0.f;
        b = (lane < 8) ? sb[lane] : 0.f;
#pragma unroll
        for (int o = 4; o > 0; o >>= 1) {
            a += __shfl_xor_sync(0xffffffffu, a, o);
            b += __shfl_xor_sync(0xffffffffu, b, o);
        }
        if (lane == 0) { sa[0] = a; sb[0] = b; }
    }
    __syncthreads();
    return make_float2(sa[0], sb[0]);
}

// ---------------- stage 1: area means (partial sums over T chunks) ------------
__global__ void __launch_bounds__(256) kMeans(const float* __restrict__ X) {
    int slab = blockIdx.x;       // k*8+b, 0..23
    int chunk = blockIdx.y;      // 0..7 (128 t each)
    size_t base = (size_t)slab * (NT * ND) + (size_t)chunk * 128 * ND;
    int col = threadIdx.x * 4;
    float4 acc = make_float4(0.f, 0.f, 0.f, 0.f);
#pragma unroll 4
    for (int t = 0; t < 128; t++) {
        float4 v = *(const float4*)(X + base + (size_t)t * ND + col);
        acc.x += v.x; acc.y += v.y; acc.z += v.z; acc.w += v.w;
    }
    *(float4*)&g_amp[(size_t)slab * 8192 + (size_t)chunk * 1024 + col] = acc;
}

// ---------------- stage 1b: reduce partial sums to means, bid-ordered ---------
__global__ void __launch_bounds__(256) kAm() {
    int bid = blockIdx.x;        // b*3 + k
    int b = bid / 3, k = bid % 3;
    int slab = k * 8 + b;
    for (int i = threadIdx.x; i < 1024; i += 256) {
        float acc = 0.f;
#pragma unroll
        for (int c = 0; c < 8; c++) acc += g_amp[(size_t)slab * 8192 + c * 1024 + i];
        g_am[bid * 1024 + i] = acc * (1.0f / 1024.0f);
    }
}

// ---------------- stage 2: pm = gelu(am @ projW + projB), W read once ---------
__global__ void __launch_bounds__(256) kPm2(const float* __restrict__ W,
                                            const float* __restrict__ bvec) {
    int col = blockIdx.x * 64 + (threadIdx.x & 63);
    int rg = threadIdx.x >> 6;   // 0..3 -> rows rg*6 .. rg*6+5
    float acc[6];
#pragma unroll
    for (int j = 0; j < 6; j++) acc[j] = 0.f;
    for (int dd = 0; dd < 1024; dd++) {
        float w = W[(size_t)dd * 1024 + col];
#pragma unroll
        for (int j = 0; j < 6; j++)
            acc[j] += g_am[(rg * 6 + j) * 1024 + dd] * w;
    }
    float bias = bvec[col];
#pragma unroll
    for (int j = 0; j < 6; j++)
        g_pm[(size_t)(rg * 6 + j) * 1024 + col] = gelu_f(acc[j] + bias);
}

// ---------------- stage 3: LN over K*d=3072 per batch -------------------------
__global__ void __launch_bounds__(256) kLN1(const float* __restrict__ gvec,
                                            const float* __restrict__ bvec) {
    int b = blockIdx.x;
    size_t base = (size_t)b * 3072;
    int i0 = threadIdx.x * 4;
    float4 v[3];
    float s = 0.f, sq = 0.f;
#pragma unroll
    for (int c = 0; c < 3; c++) {
        v[c] = *(const float4*)&g_pm[base + c * 1024 + i0];
        s += v[c].x + v[c].y + v[c].z + v[c].w;
        sq += v[c].x * v[c].x + v[c].y * v[c].y + v[c].z * v[c].z + v[c].w * v[c].w;
    }
    float2 r = blockReduce2(s, sq);
    float mu = r.x * (1.0f / 3072.0f);
    float var = r.y * (1.0f / 3072.0f) - mu * mu;
    float rstd = rsqrtf(var + 1e-5f);
#pragma unroll
    for (int c = 0; c < 3; c++) {
        int idx = c * 1024 + i0;
        float4 G = *(const float4*)(gvec + idx);
        float4 Bv = *(const float4*)(bvec + idx);
        float4 o;
        o.x = (v[c].x - mu) * rstd * G.x + Bv.x;
        o.y = (v[c].y - mu) * rstd * G.y + Bv.y;
        o.z = (v[c].z - mu) * rstd * G.z + Bv.z;
        o.w = (v[c].w - mu) * rstd * G.w + Bv.w;
        *(float4*)&g_h0[base + idx] = o;
    }
}

// ---------------- stage 4: h1 = gelu(h0 @ W1 + b1), W1 read once --------------
__global__ void __launch_bounds__(256) kH1(const float* __restrict__ W1,
                                           const float* __restrict__ b1) {
    int col = blockIdx.x * 64 + (threadIdx.x & 63);
    int bq = threadIdx.x >> 6;    // 0..3
    float a0 = 0.f, a1 = 0.f;
    const float* h0a = g_h0 + (size_t)bq * 3072;
    const float* h0b = g_h0 + (size_t)(bq + 4) * 3072;
    for (int dd = 0; dd < 3072; dd++) {
        float w = W1[(size_t)dd * 2048 + col];
        a0 += h0a[dd] * w;
        a1 += h0b[dd] * w;
    }
    float bias = b1[col];
    g_h1[(size_t)bq * 2048 + col] = gelu_f(a0 + bias);
    g_h1[(size_t)(bq + 4) * 2048 + col] = gelu_f(a1 + bias);
}

// ---------------- stage 5: logits + softmax alpha -----------------------------
__global__ void __launch_bounds__(256) kLogits(const float* __restrict__ W2,
                                               const float* __restrict__ b2,
                                               const float* __restrict__ gum,
                                               float* __restrict__ outLog) {
    __shared__ float s0[256], s1[256], s2[256];
    int b = blockIdx.x;
    int tid = threadIdx.x;
    float a0 = 0.f, a1 = 0.f, a2 = 0.f;
    for (int dd = tid; dd < 2048; dd += 256) {
        float v = g_h1[(size_t)b * 2048 + dd];
        a0 += v * W2[dd * 3 + 0];
        a1 += v * W2[dd * 3 + 1];
        a2 += v * W2[dd * 3 + 2];
    }
    s0[tid] = a0; s1[tid] = a1; s2[tid] = a2;
    __syncthreads();
    for (int off = 128; off > 0; off >>= 1) {
        if (tid < off) { s0[tid] += s0[tid + off]; s1[tid] += s1[tid + off]; s2[tid] += s2[tid + off]; }
        __syncthreads();
    }
    if (tid == 0) {
        float lg[3];
        lg[0] = s0[0] + b2[0]; lg[1] = s1[0] + b2[1]; lg[2] = s2[0] + b2[2];
        float z[3];
#pragma unroll
        for (int j = 0; j < 3; j++) {
            outLog[b * 3 + j] = lg[j];
            z[j] = (lg[j] + gum[b * 3 + j]) * 1.25f;   // / TAU (0.8)
        }
        float m = fmaxf(z[0], fmaxf(z[1], z[2]));
        float e0 = expf(z[0] - m), e1 = expf(z[1] - m), e2 = expf(z[2] - m);
        float inv = 1.0f / (e0 + e1 + e2);
        g_alpha[b * 3 + 0] = e0 * inv;
        g_alpha[b * 3 + 1] = e1 * inv;
        g_alpha[b * 3 + 2] = e2 * inv;
    }
}

// ---------------- stage 6: low = X @ V  ([64 rows x 32] tiles) ----------------
__global__ void __launch_bounds__(256) kLow(const float* __restrict__ X,
                                            const float* __restrict__ V) {
    __shared__ float Xs[64][33];
    __shared__ float Vs[32][32];
    int row0 = blockIdx.x * 64;            // global row in [0, 24576)
    int k = row0 >> 13;                    // / 8192
    int tid = threadIdx.x;
    int tx = tid & 31, ty = tid >> 5;      // tx: r, ty: row group (8)
    float acc[8];
#pragma unroll
    for (int i = 0; i < 8; i++) acc[i] = 0.f;

    for (int d0 = 0; d0 < 1024; d0 += 32) {
#pragma unroll
        for (int i = 0; i < 8; i++) {
            int idx = tid + i * 256;
            int r = idx >> 5, c = idx & 31;
            Xs[r][c] = X[(size_t)(row0 + r) * ND + d0 + c];
        }
#pragma unroll
        for (int i = 0; i < 4; i++) {
            int idx = tid + i * 256;
            int dd = idx >> 5, rr = idx & 31;
            Vs[dd][rr] = V[((size_t)k * 1024 + d0 + dd) * 32 + rr];
        }
        __syncthreads();
#pragma unroll
        for (int dd = 0; dd < 32; dd++) {
            float vv = Vs[dd][tx];
#pragma unroll
            for (int rr = 0; rr < 8; rr++) acc[rr] += Xs[rr * 8 + ty][dd] * vv;
        }
        __syncthreads();
    }
#pragma unroll
    for (int rr = 0; rr < 8; rr++)
        g_low[(size_t)(row0 + rr * 8 + ty) * 32 + tx] = acc[rr];
}

// ---------------- stage 7: routed = sum_k alpha * low @ U^T -------------------
__global__ void __launch_bounds__(256) kRouted(const float* __restrict__ U) {
    __shared__ float As[96][64];   // [p][row]
    __shared__ float Us[96][64];   // [p][col]
    int col0 = blockIdx.x * 64;
    int row0 = blockIdx.y * 64;    // row in [0, 8192)
    int tid = threadIdx.x;
    int tx = tid & 15, ty = tid >> 4;

    for (int idx = tid; idx < 6144; idx += 256) {
        int r0 = idx / 96, p = idx - r0 * 96;
        int k = p >> 5, rr = p & 31;
        int row = row0 + r0;
        int b = row >> 10;
        As[p][r0] = g_alpha[b * 3 + k] * g_low[((size_t)k * 8192 + row) * 32 + rr];
    }
    for (int idx = tid; idx < 6144; idx += 256) {
        int p = idx >> 6, e = idx & 63;
        int k = p >> 5, rr = p & 31;
        Us[p][e] = U[((size_t)k * 1024 + col0 + e) * 32 + rr];
    }
    __syncthreads();

    float acc[4][4];
#pragma unroll
    for (int i = 0; i < 4; i++)
#pragma unroll
        for (int j = 0; j < 4; j++) acc[i][j] = 0.f;

#pragma unroll 8
    for (int p = 0; p < 96; p++) {
        float4 u4 = *(const float4*)&Us[p][tx * 4];
        float a0 = As[p][ty * 4 + 0], a1 = As[p][ty * 4 + 1];
        float a2 = As[p][ty * 4 + 2], a3 = As[p][ty * 4 + 3];
        acc[0][0] += a0 * u4.x; acc[0][1] += a0 * u4.y; acc[0][2] += a0 * u4.z; acc[0][3] += a0 * u4.w;
        acc[1][0] += a1 * u4.x; acc[1][1] += a1 * u4.y; acc[1][2] += a1 * u4.z; acc[1][3] += a1 * u4.w;
        acc[2][0] += a2 * u4.x; acc[2][1] += a2 * u4.y; acc[2][2] += a2 * u4.z; acc[2][3] += a2 * u4.w;
        acc[3][0] += a3 * u4.x; acc[3][1] += a3 * u4.y; acc[3][2] += a3 * u4.z; acc[3][3] += a3 * u4.w;
    }
#pragma unroll
    for (int i = 0; i < 4; i++) {
        float4 o = make_float4(acc[i][0], acc[i][1], acc[i][2], acc[i][3]);
        *(float4*)&g_routed[(size_t)(row0 + ty * 4 + i) * ND + col0 + tx * 4] = o;
    }
}

// ============ tensor-core GEMM: 128x128 tile, 2xBF16 split, fused epilogue ====
// asel: 0=X(input), 1=routed, 2=bcomp, 3=ah
// csel: 0=bcomp, 1=ah, 2=gate, 3=m
// mode: 0=store, 1=gelu, 2=sigmoid(prevC + v + bias), 3=prevC * gelu(v)
__global__ void __launch_bounds__(256) gemm_tc(
    const float* __restrict__ Xp,
    const float* __restrict__ W, size_t wOff, size_t wStride,
    const float* __restrict__ bias,
    int asel, int csel, int mode)
{
    const int z = blockIdx.z;
    const float* Ab;
    size_t aStride;
    if (asel == 0)      { Ab = Xp;       aStride = (size_t)ROWS_K * ND; }
    else if (asel == 1) { Ab = g_routed; aStride = 0; }
    else if (asel == 2) { Ab = g_bcomp;  aStride = (size_t)ROWS_K * ND; }
    else                { Ab = g_ah;     aStride = (size_t)ROWS_K * ND; }
    float* Cb;
    if (csel == 0)      Cb = g_bcomp;
    else if (csel == 1) Cb = g_ah;
    else if (csel == 2) Cb = g_gate;
    else                Cb = g_m;

    const int row0 = blockIdx.y * 128;
    const int col0 = blockIdx.x * 128;
    Ab += (size_t)z * aStride + (size_t)row0 * ND;
    const float* Wp = W + wOff + (size_t)z * wStride + col0;
    Cb += (size_t)z * ROWS_K * ND + (size_t)row0 * ND + col0;

    // packed-bf16 smem tiles: [kpair 0..7][m or n, padded]
    __shared__ unsigned Ah[8][132], Al[8][132], Bh[8][132], Bl[8][132];

    const int tid = threadIdx.x;
    const int lane = tid & 31;
    const int wid = tid >> 5;
    const int wm = wid & 1;        // 0..1 -> m offset 64*wm
    const int wn = wid >> 1;       // 0..3 -> n offset 32*wn
    const int qrow = lane >> 2;    // 0..7
    const int qk = lane & 3;       // 0..3

    // staging (A: 2 units of float4 along k; B: 1 unit of 2k x 4n)
    const int am = tid >> 2;             // 0..63 (+64 for unit 1)
    const int ak4 = (tid & 3) * 4;       // k offset within tile
    const int bkp = tid >> 5;            // 0..7 k-pair row
    const int bn4 = (tid & 31) * 4;      // n offset

    float4 sA0, sA1, sB0, sB1;
    sA0 = *(const float4*)(Ab + (size_t)am * ND + ak4);
    sA1 = *(const float4*)(Ab + (size_t)(am + 64) * ND + ak4);
    sB0 = *(const float4*)(Wp + (size_t)(2 * bkp) * ND + bn4);
    sB1 = *(const float4*)(Wp + (size_t)(2 * bkp + 1) * ND + bn4);

    float acc[4][4][4];
#pragma unroll
    for (int i = 0; i < 4; i++)
#pragma unroll
        for (int j = 0; j < 4; j++)
#pragma unroll
            for (int q = 0; q < 4; q++) acc[i][j][q] = 0.f;

    // store stage 0 to smem
    {
        unsigned h0, l0, h1, l1;
        split2(sA0.x, sA0.y, h0, l0); split2(sA0.z, sA0.w, h1, l1);
        Ah[ak4 / 2][am] = h0; Al[ak4 / 2][am] = l0;
        Ah[ak4 / 2 + 1][am] = h1; Al[ak4 / 2 + 1][am] = l1;
        split2(sA1.x, sA1.y, h0, l0); split2(sA1.z, sA1.w, h1, l1);
        Ah[ak4 / 2][am + 64] = h0; Al[ak4 / 2][am + 64] = l0;
        Ah[ak4 / 2 + 1][am + 64] = h1; Al[ak4 / 2 + 1][am + 64] = l1;
        unsigned bh[4], bl[4];
        split2(sB0.x, sB1.x, bh[0], bl[0]);
        split2(sB0.y, sB1.y, bh[1], bl[1]);
        split2(sB0.z, sB1.z, bh[2], bl[2]);
        split2(sB0.w, sB1.w, bh[3], bl[3]);
        *(uint4*)&Bh[bkp][bn4] = make_uint4(bh[0], bh[1], bh[2], bh[3]);
        *(uint4*)&Bl[bkp][bn4] = make_uint4(bl[0], bl[1], bl[2], bl[3]);
    }
    __syncthreads();

#pragma unroll 1
    for (int kt = 0; kt < 64; kt++) {
        // load fragments from smem
        unsigned fAh[4][4], fAl[4][4], fBh[4][2], fBl[4][2];
#pragma unroll
        for (int mt = 0; mt < 4; mt++) {
            int mb = wm * 64 + mt * 16;
            fAh[mt][0] = Ah[qk][mb + qrow];     fAh[mt][1] = Ah[qk][mb + 8 + qrow];
            fAh[mt][2] = Ah[qk + 4][mb + qrow]; fAh[mt][3] = Ah[qk + 4][mb + 8 + qrow];
            fAl[mt][0] = Al[qk][mb + qrow];     fAl[mt][1] = Al[qk][mb + 8 + qrow];
            fAl[mt][2] = Al[qk + 4][mb + qrow]; fAl[mt][3] = Al[qk + 4][mb + 8 + qrow];
        }
#pragma unroll
        for (int nt = 0; nt < 4; nt++) {
            int nb = wn * 32 + nt * 8 + qrow;
            fBh[nt][0] = Bh[qk][nb]; fBh[nt][1] = Bh[qk + 4][nb];
            fBl[nt][0] = Bl[qk][nb]; fBl[nt][1] = Bl[qk + 4][nb];
        }
        // prefetch next tile from gmem
        if (kt < 63) {
            const float* An = Ab + (kt + 1) * 16;
            const float* Bn = Wp + (size_t)(kt + 1) * 16 * ND;
            sA0 = *(const float4*)(An + (size_t)am * ND + ak4);
            sA1 = *(const float4*)(An + (size_t)(am + 64) * ND + ak4);
            sB0 = *(const float4*)(Bn + (size_t)(2 * bkp) * ND + bn4);
            sB1 = *(const float4*)(Bn + (size_t)(2 * bkp + 1) * ND + bn4);
        }
        __syncthreads();   // all fragment reads complete before overwrite

        // compute: hi*hi + hi*lo + lo*hi
#pragma unroll
        for (int mt = 0; mt < 4; mt++)
#pragma unroll
            for (int nt = 0; nt < 4; nt++) {
                mma16816(acc[mt][nt], fAh[mt], fBh[nt][0], fBh[nt][1]);
                mma16816(acc[mt][nt], fAh[mt], fBl[nt][0], fBl[nt][1]);
                mma16816(acc[mt][nt], fAl[mt], fBh[nt][0], fBh[nt][1]);
            }

        if (kt < 63) {
            unsigned h0, l0, h1, l1;
            split2(sA0.x, sA0.y, h0, l0); split2(sA0.z, sA0.w, h1, l1);
            Ah[ak4 / 2][am] = h0; Al[ak4 / 2][am] = l0;
            Ah[ak4 / 2 + 1][am] = h1; Al[ak4 / 2 + 1][am] = l1;
            split2(sA1.x, sA1.y, h0, l0); split2(sA1.z, sA1.w, h1, l1);
            Ah[ak4 / 2][am + 64] = h0; Al[ak4 / 2][am + 64] = l0;
            Ah[ak4 / 2 + 1][am + 64] = h1; Al[ak4 / 2 + 1][am + 64] = l1;
            unsigned bh[4], bl[4];
            split2(sB0.x, sB1.x, bh[0], bl[0]);
            split2(sB0.y, sB1.y, bh[1], bl[1]);
            split2(sB0.z, sB1.z, bh[2], bl[2]);
            split2(sB0.w, sB1.w, bh[3], bl[3]);
            *(uint4*)&Bh[bkp][bn4] = make_uint4(bh[0], bh[1], bh[2], bh[3]);
            *(uint4*)&Bl[bkp][bn4] = make_uint4(bl[0], bl[1], bl[2], bl[3]);
            __syncthreads();
        }
    }

    // ---------------- fused epilogue ----------------
#pragma unroll
    for (int mt = 0; mt < 4; mt++) {
        int rbase = wm * 64 + mt * 16 + qrow;
#pragma unroll
        for (int half = 0; half < 2; half++) {
            int r = rbase + half * 8;
#pragma unroll
            for (int nt = 0; nt < 4; nt++) {
                int c = wn * 32 + nt * 8 + 2 * qk;
                float v0 = acc[mt][nt][half * 2 + 0];
                float v1 = acc[mt][nt][half * 2 + 1];
                float* cp = Cb + (size_t)r * ND + c;
                if (mode == 0) {
                    *(float2*)cp = make_float2(v0, v1);
                } else if (mode == 1) {
                    *(float2*)cp = make_float2(gelu_f(v0), gelu_f(v1));
                } else if (mode == 2) {
                    float2 p = *(float2*)cp;
                    float b0 = bias[(size_t)z * ND + col0 + c];
                    float b1 = bias[(size_t)z * ND + col0 + c + 1];
                    *(float2*)cp = make_float2(sigm_f(p.x + v0 + b0), sigm_f(p.y + v1 + b1));
                } else {
                    float2 p = *(float2*)cp;
                    *(float2*)cp = make_float2(p.x * gelu_f(v0), p.y * gelu_f(v1));
                }
            }
        }
    }
}

// ---------------- final: y = LN(x + (1-g)*b + g*m) * lng + lnb ----------------
__global__ void __launch_bounds__(256) kFinal(const float* __restrict__ X,
                                              const float* __restrict__ cg,
                                              const float* __restrict__ cb,
                                              float* __restrict__ out) {
    size_t row = blockIdx.x;
    int k = (int)(row >> 13);
    size_t base = row * ND + threadIdx.x * 4;
    float4 x  = *(const float4*)(X + base);
    float4 bc = *(const float4*)(g_bcomp + base);
    float4 gv = *(const float4*)(g_gate + base);
    float4 mv = *(const float4*)(g_m + base);
    float4 v;
    v.x = x.x + (1.f - gv.x) * bc.x + gv.x * mv.x;
    v.y = x.y + (1.f - gv.y) * bc.y + gv.y * mv.y;
    v.z = x.z + (1.f - gv.z) * bc.z + gv.z * mv.z;
    v.w = x.w + (1.f - gv.w) * bc.w + gv.w * mv.w;
    float s = v.x + v.y + v.z + v.w;
    float sq = v.x * v.x + v.y * v.y + v.z * v.z + v.w * v.w;
    float2 r = blockReduce2(s, sq);
    float mu = r.x * (1.0f / 1024.0f);
    float var = r.y * (1.0f / 1024.0f) - mu * mu;
    float rstd = rsqrtf(var + 1e-5f);
    int ci = k * 1024 + threadIdx.x * 4;
    float4 G = *(const float4*)(cg + ci);
    float4 Bv = *(const float4*)(cb + ci);
    float4 o;
    o.x = (v.x - mu) * rstd * G.x + Bv.x;
    o.y = (v.y - mu) * rstd * G.y + Bv.y;
    o.z = (v.z - mu) * rstd * G.z + Bv.z;
    o.w = (v.w - mu) * rstd * G.w + Bv.w;
    *(float4*)(out + base) = o;
}

// ---------------- launch ------------------------------------------------------
extern "C" void kernel_launch(void* const* d_in, const int* in_sizes, int n_in,
                              void* d_out, int out_size) {
    (void)in_sizes; (void)n_in; (void)out_size;
    const float* X    = (const float*)d_in[0];
    const float* gum  = (const float*)d_in[1];
    const float* prW  = (const float*)d_in[2];
    const float* prB  = (const float*)d_in[3];
    const float* hlg  = (const float*)d_in[4];
    const float* hlb  = (const float*)d_in[5];
    const float* W1   = (const float*)d_in[6];
    const float* b1   = (const float*)d_in[7];
    const float* W2   = (const float*)d_in[8];
    const float* b2   = (const float*)d_in[9];
    const float* U    = (const float*)d_in[10];
    const float* V    = (const float*)d_in[11];
    const float* Wb   = (const float*)d_in[12];
    const float* Wa   = (const float*)d_in[13];
    const float* Wg   = (const float*)d_in[14];
    const float* bg   = (const float*)d_in[15];
    const float* Wm1  = (const float*)d_in[16];
    const float* Wm2  = (const float*)d_in[17];
    const float* clg  = (const float*)d_in[18];
    const float* clb  = (const float*)d_in[19];
    float* out = (float*)d_out;

    // controller
    kMeans<<<dim3(24, 8), 256>>>(X);
    kAm<<<24, 256>>>();
    kPm2<<<16, 256>>>(prW, prB);
    kLN1<<<8, 256>>>(hlg, hlb);
    kH1<<<32, 256>>>(W1, b1);
    kLogits<<<8, 256>>>(W2, b2, gum, out + YN);

    // router
    kLow<<<ROWS_ALL / 64, 256>>>(X, V);
    kRouted<<<dim3(16, 128), 256>>>(U);

    // columns: pass 1
    dim3 gg(8, 64, 3);
    gemm_tc<<<gg, 256>>>(X, Wb,  0,       1048576, nullptr, 0, 0, 1); // bcomp = gelu(X@Wb)
    gemm_tc<<<gg, 256>>>(X, Wa,  0,       1048576, nullptr, 1, 1, 1); // ah = gelu(routed@Wa)
    gemm_tc<<<gg, 256>>>(X, Wg,  0,       2097152, nullptr, 0, 2, 0); // gate = X@Wg_top (raw)
    gemm_tc<<<gg, 256>>>(X, Wg,  1048576, 2097152, bg,      1, 2, 2); // gate = sigmoid(. + routed@Wg_bot + bg)
    // pass 2
    gemm_tc<<<gg, 256>>>(X, Wm1, 0,       1048576, nullptr, 2, 3, 1); // m = gelu(bcomp@Wm1)
    gemm_tc<<<gg, 256>>>(X, Wm2, 0,       1048576, nullptr, 3, 3, 3); // m *= gelu(ah@Wm2)

    // final LN + output
    kFinal<<<ROWS_ALL, 256>>>(X, clg, clb, out);
}